// round 5
// baseline (speedup 1.0000x reference)
#include <cuda_runtime.h>
#include <math.h>
#include <stdint.h>

#define NPTS   32768
#define NE     1024
#define EDIM   256
#define ZSIZE  8388608
#define OUT_ZQ   1
#define OUT_PERP (1 + ZSIZE)
#define OUT_IDX  (2 + ZSIZE)
#define MARGIN   2.5e-3f
#define CAP      32

__device__ int   g_idx[NPTS];
__device__ float g_enorm[NE];
__device__ int   g_counts[NE];
__device__ float g_loss_sum;

__device__ __forceinline__ uint32_t f2tf(float v) {
    uint32_t r; asm("cvt.rna.tf32.f32 %0, %1;" : "=r"(r) : "f"(v)); return r;
}
__device__ __forceinline__ float tfv(float v) { return __uint_as_float(f2tf(v)); }

// order-preserving float <-> uint32
__device__ __forceinline__ uint32_t encF(float f) {
    uint32_t u = __float_as_uint(f);
    return (u & 0x80000000u) ? ~u : (u | 0x80000000u);
}
__device__ __forceinline__ float decF(uint32_t u) {
    u = (u & 0x80000000u) ? (u & 0x7FFFFFFFu) : ~u;
    return __uint_as_float(u);
}

#define MMA_TF32(d, a, b) \
    asm volatile("mma.sync.aligned.m16n8k8.row.col.f32.tf32.tf32.f32 " \
        "{%0,%1,%2,%3}, {%4,%5,%6,%7}, {%8,%9}, {%0,%1,%2,%3};" \
        : "+f"((d)[0]), "+f"((d)[1]), "+f"((d)[2]), "+f"((d)[3]) \
        : "r"((a)[0]), "r"((a)[1]), "r"((a)[2]), "r"((a)[3]), \
          "r"((b)[0]), "r"((b)[1]))

// ======================= enorm: exact ||e||^2 + zero accumulators =======================
__global__ void enorm_kernel(const float* __restrict__ w) {
    int c = blockIdx.x * blockDim.x + threadIdx.x;
    g_counts[c] = 0;
    if (c == 0) g_loss_sum = 0.f;
    const float* row = w + (size_t)c * EDIM;
    float s = 0.f;
#pragma unroll 8
    for (int k = 0; k < EDIM; k++) {
        float v = row[k];
        s = __fadd_rn(s, __fmul_rn(v, v));
    }
    g_enorm[c] = s;
}

// ======================= fused HMMA + candidate select + exact rescore =======================
// CTA: 128 points x 1024 codes (8 tiles of 128 codes). A (128x256 tf32) smem-
// resident (stride 260). B double-buffered 128x32 chunks (stride 36).
// 8 warps 2(M)x4(N), per-warp 4x4 m16n8 frags. Epilogue per tile: smem
// prefix-min + margin candidate append. Tail: exact fp32 chains on candidates.
#define AST 260
#define BST 36
#define A_EL (128 * AST)
#define B_EL (128 * BST)
// floats: A + 2B + sw(1024); then tail arrays
#define SMEM_MMA ((A_EL + 2 * B_EL + 1024) * 4 + 1024 + 512 + 512 + 512 + CAP * 128 * 4)

__global__ __launch_bounds__(256, 1)
void mma_kernel(const float* __restrict__ z, const float* __restrict__ w,
                float* __restrict__ out) {
    extern __shared__ float sm[];
    float* A_s  = sm;
    float* B_s  = sm + A_EL;                       // [2][B_EL]; start reused as staging
    float* sw_s = B_s + 2 * B_EL;                  // [1024]
    unsigned long long* best = (unsigned long long*)(sw_s + 1024);   // [128]
    uint32_t* smin = (uint32_t*)(best + 128);      // [128]
    int*      ccnt = (int*)(smin + 128);           // [128]
    float*    szs  = (float*)(ccnt + 128);         // [128]
    uint32_t* cand = (uint32_t*)(szs + 128);       // [128][CAP]

    int tid = threadIdx.x;
    int lane = tid & 31, wid = tid >> 5;
    int g = lane >> 2, t = lane & 3;
    int wm = wid >> 2, wn = wid & 3;
    int n0 = blockIdx.x * 128;
    int b = n0 >> 10, hw0 = n0 & 1023;
    const float* zb = z + (size_t)b * 262144 + hw0;

    if (tid < 128) {
        smin[tid] = 0xFFFFFFFFu;
        ccnt[tid] = 0;
        best[tid] = 0xFFFFFFFFFFFFFFFFull;
    }
    for (int i = tid; i < NE; i += 256) sw_s[i] = g_enorm[i];

    // ---- A fill: stage 32-point chunks through B_s region, cvt tf32 ----
    float* tile = B_s;   // 256*33 = 8448 floats <= 2*B_EL
    for (int ch = 0; ch < 4; ch++) {
        int m0 = ch * 32;
#pragma unroll
        for (int i = 0; i < 8; i++) {
            int idx = tid + i * 256;
            int c = idx >> 3, q = idx & 7;
            float4 v = *(const float4*)(zb + (size_t)c * 1024 + m0 + q * 4);
            tile[c * 33 + q * 4 + 0] = v.x; tile[c * 33 + q * 4 + 1] = v.y;
            tile[c * 33 + q * 4 + 2] = v.z; tile[c * 33 + q * 4 + 3] = v.w;
        }
        __syncthreads();
#pragma unroll
        for (int i = 0; i < 8; i++) {
            int idx = tid + i * 256;
            int m = idx >> 6, c4 = idx & 63;
            float4 o;
            o.x = tfv(tile[(c4 * 4 + 0) * 33 + m]);
            o.y = tfv(tile[(c4 * 4 + 1) * 33 + m]);
            o.z = tfv(tile[(c4 * 4 + 2) * 33 + m]);
            o.w = tfv(tile[(c4 * 4 + 3) * 33 + m]);
            *(float4*)(A_s + (m0 + m) * AST + c4 * 4) = o;
        }
        __syncthreads();
    }

    for (int j = 0; j < 8; j++) {
        float acc[4][4][4];
#pragma unroll
        for (int mt = 0; mt < 4; mt++)
#pragma unroll
            for (int nt = 0; nt < 4; nt++)
#pragma unroll
                for (int q = 0; q < 4; q++) acc[mt][nt][q] = 0.f;

        // prologue: B chunk kc=0 into buf 0
        {
            const float* wp = w + (size_t)(j * 128) * 256;
#pragma unroll
            for (int i = 0; i < 4; i++) {
                int idx = tid + i * 256;
                int c = idx >> 3, kq = idx & 7;
                float4 v = *(const float4*)(wp + (size_t)c * 256 + kq * 4);
                *(float4*)(B_s + c * BST + kq * 4) =
                    make_float4(tfv(v.x), tfv(v.y), tfv(v.z), tfv(v.w));
            }
        }
        __syncthreads();

        for (int kc = 0; kc < 8; kc++) {
            int buf = kc & 1;
            // prefetch next chunk into registers (hide LDG behind mma)
            float4 pf[4];
            if (kc < 7) {
                const float* wp = w + (size_t)(j * 128) * 256 + (kc + 1) * 32;
#pragma unroll
                for (int i = 0; i < 4; i++) {
                    int idx = tid + i * 256;
                    int c = idx >> 3, kq = idx & 7;
                    pf[i] = *(const float4*)(wp + (size_t)c * 256 + kq * 4);
                }
            }
            const float* Bb = B_s + buf * B_EL;
#pragma unroll
            for (int ks = 0; ks < 4; ks++) {
                int k0 = kc * 32 + ks * 8;
                uint32_t bf[4][2];
#pragma unroll
                for (int nt = 0; nt < 4; nt++) {
                    int code = wn * 32 + nt * 8 + g;
                    bf[nt][0] = __float_as_uint(Bb[code * BST + ks * 8 + t]);
                    bf[nt][1] = __float_as_uint(Bb[code * BST + ks * 8 + t + 4]);
                }
#pragma unroll
                for (int mt = 0; mt < 4; mt++) {
                    int row = wm * 64 + mt * 16 + g;
                    uint32_t af[4];
                    af[0] = __float_as_uint(A_s[row * AST + k0 + t]);
                    af[1] = __float_as_uint(A_s[(row + 8) * AST + k0 + t]);
                    af[2] = __float_as_uint(A_s[row * AST + k0 + t + 4]);
                    af[3] = __float_as_uint(A_s[(row + 8) * AST + k0 + t + 4]);
#pragma unroll
                    for (int nt = 0; nt < 4; nt++)
                        MMA_TF32(acc[mt][nt], af, bf[nt]);
                }
            }
            if (kc < 7) {
#pragma unroll
                for (int i = 0; i < 4; i++) {
                    int idx = tid + i * 256;
                    int c = idx >> 3, kq = idx & 7;
                    *(float4*)(B_s + (buf ^ 1) * B_EL + c * BST + kq * 4) =
                        make_float4(tfv(pf[i].x), tfv(pf[i].y), tfv(pf[i].z), tfv(pf[i].w));
                }
            }
            __syncthreads();
        }

        // ---- epilogue phase 1: per-row tile min -> smem prefix min ----
        float rm[8];
#pragma unroll
        for (int r = 0; r < 8; r++) rm[r] = 3.4e38f;
#pragma unroll
        for (int nt = 0; nt < 4; nt++) {
            int colg = j * 128 + wn * 32 + nt * 8 + 2 * t;
            float sw0 = sw_s[colg], sw1 = sw_s[colg + 1];
#pragma unroll
            for (int mt = 0; mt < 4; mt++) {
                float s00 = fmaf(-2.f, acc[mt][nt][0], sw0);
                float s01 = fmaf(-2.f, acc[mt][nt][1], sw1);
                float s10 = fmaf(-2.f, acc[mt][nt][2], sw0);
                float s11 = fmaf(-2.f, acc[mt][nt][3], sw1);
                rm[mt * 2]     = fminf(rm[mt * 2],     fminf(s00, s01));
                rm[mt * 2 + 1] = fminf(rm[mt * 2 + 1], fminf(s10, s11));
            }
        }
#pragma unroll
        for (int r = 0; r < 8; r++) {
            int row = wm * 64 + (r >> 1) * 16 + (r & 1) * 8 + g;
            atomicMin(&smin[row], encF(rm[r]));
        }
        __syncthreads();

        // ---- epilogue phase 2: margin candidates ----
        float thr[8];
#pragma unroll
        for (int r = 0; r < 8; r++) {
            int row = wm * 64 + (r >> 1) * 16 + (r & 1) * 8 + g;
            thr[r] = decF(smin[row]) + MARGIN;
        }
#pragma unroll
        for (int nt = 0; nt < 4; nt++) {
            int colg = j * 128 + wn * 32 + nt * 8 + 2 * t;
            float sw0 = sw_s[colg], sw1 = sw_s[colg + 1];
#pragma unroll
            for (int mt = 0; mt < 4; mt++) {
                int r0 = wm * 64 + mt * 16 + g;
                float s00 = fmaf(-2.f, acc[mt][nt][0], sw0);
                float s01 = fmaf(-2.f, acc[mt][nt][1], sw1);
                float s10 = fmaf(-2.f, acc[mt][nt][2], sw0);
                float s11 = fmaf(-2.f, acc[mt][nt][3], sw1);
                if (s00 <= thr[mt * 2]) {
                    int ps = atomicAdd(&ccnt[r0], 1);
                    if (ps < CAP) cand[r0 * CAP + ps] = colg;
                }
                if (s01 <= thr[mt * 2]) {
                    int ps = atomicAdd(&ccnt[r0], 1);
                    if (ps < CAP) cand[r0 * CAP + ps] = colg + 1;
                }
                if (s10 <= thr[mt * 2 + 1]) {
                    int ps = atomicAdd(&ccnt[r0 + 8], 1);
                    if (ps < CAP) cand[(r0 + 8) * CAP + ps] = colg;
                }
                if (s11 <= thr[mt * 2 + 1]) {
                    int ps = atomicAdd(&ccnt[r0 + 8], 1);
                    if (ps < CAP) cand[(r0 + 8) * CAP + ps] = colg + 1;
                }
            }
        }
        __syncthreads();
    }

    // ---- exact ||z||^2 per point (ascending-k fp32 chain, coalesced) ----
    if (tid < 128) {
        const float* zc = zb + tid;
        float s = 0.f;
#pragma unroll 8
        for (int k = 0; k < EDIM; k++) {
            float v = zc[(size_t)k * 1024];
            s = __fadd_rn(s, __fmul_rn(v, v));
        }
        szs[tid] = s;
    }
    __syncthreads();

    // ---- exact rescore of candidates: 2 threads per point ----
    {
        int p = tid & 127, half = tid >> 7;
        int cnt = ccnt[p];
        if (cnt == 1) {
            if (half == 0) best[p] = (unsigned long long)cand[p * CAP];
        } else {
            const float* zc = zb + p;
            float szl = szs[p];
            int lim = (cnt <= CAP) ? cnt : 0;
            if (cnt <= CAP) {
                for (int ci = half; ci < lim; ci += 2) {
                    int code = cand[p * CAP + ci];
                    const float* wr = w + (size_t)code * EDIM;
                    float dot = 0.f;
#pragma unroll 8
                    for (int k = 0; k < EDIM; k++)
                        dot = fmaf(zc[(size_t)k * 1024], wr[k], dot);
                    float d = __fsub_rn(__fadd_rn(szl, sw_s[code]), __fmul_rn(2.f, dot));
                    unsigned long long pk =
                        ((unsigned long long)encF(d) << 32) | (uint32_t)code;
                    atomicMin(&best[p], pk);
                }
            } else {
                // overflow fallback (≈never): exact scan of all codes
                for (int code = half; code < NE; code += 2) {
                    const float* wr = w + (size_t)code * EDIM;
                    float dot = 0.f;
#pragma unroll 8
                    for (int k = 0; k < EDIM; k++)
                        dot = fmaf(zc[(size_t)k * 1024], wr[k], dot);
                    float d = __fsub_rn(__fadd_rn(szl, sw_s[code]), __fmul_rn(2.f, dot));
                    unsigned long long pk =
                        ((unsigned long long)encF(d) << 32) | (uint32_t)code;
                    atomicMin(&best[p], pk);
                }
            }
        }
    }
    __syncthreads();
    if (tid < 128) {
        int bc = (int)(best[tid] & 0xFFFFFFFFu);
        g_idx[n0 + tid] = bc;
        out[OUT_IDX + n0 + tid] = (float)bc;
        atomicAdd(&g_counts[bc], 1);
    }
}

// ======================= gather: z_q_out (STE) + loss =======================
__global__ __launch_bounds__(256) void gather_kernel(const float* __restrict__ z,
                                                     const float* __restrict__ w,
                                                     float* __restrict__ out) {
    __shared__ float wrow[32][257];
    __shared__ int ids[32];
    __shared__ float red[8];
    int t = threadIdx.x, lane = t & 31, wrp = t >> 5;
    int n0 = blockIdx.x * 32;
    int b = n0 >> 10, hw0 = n0 & 1023;

    if (t < 32) ids[t] = g_idx[n0 + t];
    __syncthreads();
#pragma unroll
    for (int i = 0; i < 8; i++) {
        int idx = t + i * 256;
        int r = idx >> 6, q = idx & 63;
        float4 v = *(const float4*)(w + (size_t)ids[r] * 256 + q * 4);
        wrow[r][q * 4 + 0] = v.x; wrow[r][q * 4 + 1] = v.y;
        wrow[r][q * 4 + 2] = v.z; wrow[r][q * 4 + 3] = v.w;
    }
    __syncthreads();

    float loss = 0.f;
    const float* zb = z + (size_t)b * 262144 + hw0;
    float* ob = out + OUT_ZQ + (size_t)b * 262144 + hw0;
    for (int c = wrp; c < 256; c += 8) {
        float zv = zb[(size_t)c * 1024 + lane];
        float q = wrow[lane][c];
        float d = __fsub_rn(q, zv);
        ob[(size_t)c * 1024 + lane] = __fadd_rn(zv, d);
        loss += d * d;
    }
#pragma unroll
    for (int off = 16; off; off >>= 1) loss += __shfl_down_sync(0xffffffffu, loss, off);
    if (lane == 0) red[wrp] = loss;
    __syncthreads();
    if (wrp == 0) {
        float v = (lane < 8) ? red[lane] : 0.f;
#pragma unroll
        for (int off = 4; off; off >>= 1) v += __shfl_down_sync(0xffffffffu, v, off);
        if (lane == 0) atomicAdd(&g_loss_sum, v);
    }
}

// ======================= finalize =======================
__global__ void finalize_kernel(float* __restrict__ out) {
    int t = threadIdx.x;
    float em = (float)g_counts[t] * (1.0f / 32768.f);
    float s = em * logf(em + 1e-10f);
#pragma unroll
    for (int off = 16; off; off >>= 1) s += __shfl_down_sync(0xffffffffu, s, off);
    __shared__ float red[32];
    int lane = t & 31, wid = t >> 5;
    if (lane == 0) red[wid] = s;
    __syncthreads();
    if (wid == 0) {
        float v = red[lane];
#pragma unroll
        for (int off = 16; off; off >>= 1) v += __shfl_down_sync(0xffffffffu, v, off);
        if (lane == 0) {
            out[0] = g_loss_sum * (1.25f / 8388608.f);
            out[OUT_PERP] = expf(-v);
        }
    }
}

// ======================= launch =======================
extern "C" void kernel_launch(void* const* d_in, const int* in_sizes, int n_in,
                              void* d_out, int out_size) {
    const float* z = (const float*)d_in[0];
    const float* w = (const float*)d_in[1];
    float* out = (float*)d_out;

    cudaFuncSetAttribute(mma_kernel, cudaFuncAttributeMaxDynamicSharedMemorySize, SMEM_MMA);

    enorm_kernel<<<4, 256>>>(w);
    mma_kernel<<<NPTS / 128, 256, SMEM_MMA>>>(z, w, out);
    gather_kernel<<<NPTS / 32, 256>>>(z, w, out);
    finalize_kernel<<<1, 1024>>>(out);
}